// round 1
// baseline (speedup 1.0000x reference)
#include <cuda_runtime.h>
#include <cstdint>

// Problem constants
#define N_SRC1  292864
#define N_DST1  11264
#define N_E1    281600
#define N_DST2  1024
#define N_E2    10240
#define IN_DIM  256
#define H_DIM   256
#define C_DIM   47

// Scratch (device globals — no allocation allowed)
__device__ float g_hneigh1[N_DST1 * H_DIM];   // mean-aggregated neighbors, layer 1 (input features)
__device__ float g_h[N_DST1 * H_DIM];         // relu(layer-1 output)
__device__ float g_hneigh2[N_DST2 * H_DIM];   // mean-aggregated neighbors, layer 2

// ---------------------------------------------------------------------------
// Segment mean aggregation. dst is sorted ascending; one block per dst node.
// Block = 64 threads, each owns 4 contiguous floats (float4) of the 256-dim row.
// ---------------------------------------------------------------------------
__global__ void agg_mean_kernel(const float* __restrict__ feat,
                                const int* __restrict__ src_idx,
                                const int* __restrict__ dst_idx,
                                int n_edges,
                                float* __restrict__ out)
{
    const int d = blockIdx.x;

    // lower_bound(dst_idx, d)
    int lo = 0, hi = n_edges;
    while (lo < hi) { int mid = (lo + hi) >> 1; if (__ldg(&dst_idx[mid]) < d) lo = mid + 1; else hi = mid; }
    const int start = lo;
    // upper_bound(dst_idx, d)
    hi = n_edges;
    while (lo < hi) { int mid = (lo + hi) >> 1; if (__ldg(&dst_idx[mid]) <= d) lo = mid + 1; else hi = mid; }
    const int end = lo;

    const int t = threadIdx.x;           // 0..63
    float4 acc = make_float4(0.f, 0.f, 0.f, 0.f);

    for (int e = start; e < end; ++e) {
        const int s = __ldg(&src_idx[e]);
        const float4 v = *reinterpret_cast<const float4*>(&feat[(size_t)s * 256 + t * 4]);
        acc.x += v.x; acc.y += v.y; acc.z += v.z; acc.w += v.w;
    }

    const int deg = end - start;
    const float inv = (deg > 0) ? 1.0f / (float)deg : 0.0f;
    acc.x *= inv; acc.y *= inv; acc.z *= inv; acc.w *= inv;

    *reinterpret_cast<float4*>(&out[(size_t)d * 256 + t * 4]) = acc;
}

// ---------------------------------------------------------------------------
// Layer-1 fused GEMM: h = relu( [x_dst | h_neigh] @ [W_self ; W_neigh] + b )
// M = 11264 (88 tiles of 128), N = 256 (2 tiles of 128), K = 512.
// Classic SGEMM: 128x128 block tile, BK=8, 256 threads, 8x8 register tile.
// ---------------------------------------------------------------------------
#define BM 128
#define BN 128
#define BK 8
#define TM 8
#define TN 8

__global__ __launch_bounds__(256) void gemm1_relu_kernel(
    const float* __restrict__ x,        // [N_SRC1, 256] (rows [0,11264) used)
    const float* __restrict__ hneigh,   // [N_DST1, 256]
    const float* __restrict__ Wself,    // [256, 256]
    const float* __restrict__ Wneigh,   // [256, 256]
    const float* __restrict__ bias,     // [256]
    float* __restrict__ out)            // [N_DST1, 256]
{
    const int bx = blockIdx.x;  // 0..1  (N tiles)
    const int by = blockIdx.y;  // 0..87 (M tiles)

    __shared__ float As[BK][BM];
    __shared__ float Bs[BK][BN];

    const int tid  = threadIdx.x;
    const int tcol = tid & 15;       // 0..15
    const int trow = tid >> 4;       // 0..15

    // A-load mapping: 128 rows x 8 cols = 1024 elems; thread loads one float4
    const int a_row = tid >> 1;            // 0..127
    const int a_col = (tid & 1) * 4;       // 0 or 4
    // B-load mapping: 8 rows x 128 cols; thread loads one float4
    const int b_row = tid >> 5;            // 0..7
    const int b_col = (tid & 31) * 4;      // 0..124

    float acc[TM][TN];
#pragma unroll
    for (int i = 0; i < TM; ++i)
#pragma unroll
        for (int j = 0; j < TN; ++j) acc[i][j] = 0.f;

    for (int k0 = 0; k0 < 512; k0 += BK) {
        const bool first_half = (k0 < 256);
        const float* Asrc = first_half ? x : hneigh;
        const float* Bsrc = first_half ? Wself : Wneigh;
        const int kk = k0 & 255;

        // Load A tile (transposed into As[k][m])
        {
            const float4 av = *reinterpret_cast<const float4*>(
                &Asrc[(size_t)(by * BM + a_row) * 256 + kk + a_col]);
            As[a_col + 0][a_row] = av.x;
            As[a_col + 1][a_row] = av.y;
            As[a_col + 2][a_row] = av.z;
            As[a_col + 3][a_row] = av.w;
        }
        // Load B tile
        {
            const float4 bv = *reinterpret_cast<const float4*>(
                &Bsrc[(size_t)(kk + b_row) * 256 + bx * BN + b_col]);
            *reinterpret_cast<float4*>(&Bs[b_row][b_col]) = bv;
        }
        __syncthreads();

#pragma unroll
        for (int k = 0; k < BK; ++k) {
            float ar[TM], br[TN];
#pragma unroll
            for (int i = 0; i < TM; ++i) ar[i] = As[k][trow * TM + i];
#pragma unroll
            for (int j = 0; j < TN; ++j) br[j] = Bs[k][tcol * TN + j];
#pragma unroll
            for (int i = 0; i < TM; ++i)
#pragma unroll
                for (int j = 0; j < TN; ++j)
                    acc[i][j] += ar[i] * br[j];
        }
        __syncthreads();
    }

    // Epilogue: +bias, relu, store (float4)
#pragma unroll
    for (int i = 0; i < TM; ++i) {
        const int grow = by * BM + trow * TM + i;
#pragma unroll
        for (int j = 0; j < TN; j += 4) {
            const int gcol = bx * BN + tcol * TN + j;
            float4 v;
            v.x = acc[i][j + 0] + __ldg(&bias[gcol + 0]);
            v.y = acc[i][j + 1] + __ldg(&bias[gcol + 1]);
            v.z = acc[i][j + 2] + __ldg(&bias[gcol + 2]);
            v.w = acc[i][j + 3] + __ldg(&bias[gcol + 3]);
            v.x = fmaxf(v.x, 0.f); v.y = fmaxf(v.y, 0.f);
            v.z = fmaxf(v.z, 0.f); v.w = fmaxf(v.w, 0.f);
            *reinterpret_cast<float4*>(&out[(size_t)grow * 256 + gcol]) = v;
        }
    }
}

// ---------------------------------------------------------------------------
// Layer-2 output GEMM: out[1024,47] = h[:1024] @ Ws2 + hneigh2 @ Wn2 + b2
// One block per output row; 64 threads (47 active in compute).
// ---------------------------------------------------------------------------
__global__ __launch_bounds__(64) void gemm2_kernel(
    const float* __restrict__ h,        // [N_DST1, 256]
    const float* __restrict__ hneigh2,  // [N_DST2, 256]
    const float* __restrict__ Ws,       // [256, 47]
    const float* __restrict__ Wn,       // [256, 47]
    const float* __restrict__ bias,     // [47]
    float* __restrict__ out)            // [N_DST2, 47]
{
    const int r = blockIdx.x;
    __shared__ float a_self[256];
    __shared__ float a_neigh[256];

    const int t = threadIdx.x;
    for (int i = t; i < 256; i += 64) {
        a_self[i]  = h[(size_t)r * 256 + i];
        a_neigh[i] = hneigh2[(size_t)r * 256 + i];
    }
    __syncthreads();

    if (t < C_DIM) {
        float acc = __ldg(&bias[t]);
#pragma unroll 8
        for (int k = 0; k < 256; ++k) {
            acc += a_self[k]  * __ldg(&Ws[k * C_DIM + t]);
            acc += a_neigh[k] * __ldg(&Wn[k * C_DIM + t]);
        }
        out[(size_t)r * C_DIM + t] = acc;
    }
}

// ---------------------------------------------------------------------------
// Launch
// ---------------------------------------------------------------------------
extern "C" void kernel_launch(void* const* d_in, const int* in_sizes, int n_in,
                              void* d_out, int out_size)
{
    const float* x       = (const float*)d_in[0];
    const int*   src1    = (const int*)  d_in[1];
    const int*   dst1    = (const int*)  d_in[2];
    const int*   src2    = (const int*)  d_in[3];
    const int*   dst2    = (const int*)  d_in[4];
    const float* Wself1  = (const float*)d_in[5];
    const float* Wneigh1 = (const float*)d_in[6];
    const float* b1      = (const float*)d_in[7];
    const float* Wself2  = (const float*)d_in[8];
    const float* Wneigh2 = (const float*)d_in[9];
    const float* b2      = (const float*)d_in[10];
    float* out = (float*)d_out;

    float* hneigh1; cudaGetSymbolAddress((void**)&hneigh1, g_hneigh1);
    float* hbuf;    cudaGetSymbolAddress((void**)&hbuf,    g_h);
    float* hneigh2; cudaGetSymbolAddress((void**)&hneigh2, g_hneigh2);

    // Layer 1: neighbor mean aggregation over x
    agg_mean_kernel<<<N_DST1, 64>>>(x, src1, dst1, N_E1, hneigh1);

    // Layer 1: fused GEMM + bias + relu
    dim3 g1(H_DIM / BN, N_DST1 / BM);   // (2, 88)
    gemm1_relu_kernel<<<g1, 256>>>(x, hneigh1, Wself1, Wneigh1, b1, hbuf);

    // Layer 2: neighbor mean aggregation over h
    agg_mean_kernel<<<N_DST2, 64>>>(hbuf, src2, dst2, N_E2, hneigh2);

    // Layer 2: output GEMM
    gemm2_kernel<<<N_DST2, 64>>>(hbuf, hneigh2, Wself2, Wneigh2, b2, out);
}

// round 2
// speedup vs baseline: 1.2019x; 1.2019x over previous
#include <cuda_runtime.h>
#include <cstdint>

// Problem constants
#define N_SRC1  292864
#define N_DST1  11264
#define N_E1    281600
#define N_DST2  1024
#define N_E2    10240
#define IN_DIM  256
#define H_DIM   256
#define C_DIM   47

// Scratch (device globals — no allocation allowed)
__device__ float g_hneigh1[N_DST1 * H_DIM];
__device__ float g_h[N_DST1 * H_DIM];
__device__ float g_hneigh2[N_DST2 * H_DIM];

// ---------------------------------------------------------------------------
// Segment mean aggregation. dst sorted ascending; one block per dst node.
// ---------------------------------------------------------------------------
__global__ void agg_mean_kernel(const float* __restrict__ feat,
                                const int* __restrict__ src_idx,
                                const int* __restrict__ dst_idx,
                                int n_edges,
                                float* __restrict__ out)
{
    const int d = blockIdx.x;

    int lo = 0, hi = n_edges;
    while (lo < hi) { int mid = (lo + hi) >> 1; if (__ldg(&dst_idx[mid]) < d) lo = mid + 1; else hi = mid; }
    const int start = lo;
    hi = n_edges;
    while (lo < hi) { int mid = (lo + hi) >> 1; if (__ldg(&dst_idx[mid]) <= d) lo = mid + 1; else hi = mid; }
    const int end = lo;

    const int t = threadIdx.x;           // 0..63
    float4 acc = make_float4(0.f, 0.f, 0.f, 0.f);

    for (int e = start; e < end; ++e) {
        const int s = __ldg(&src_idx[e]);
        const float4 v = *reinterpret_cast<const float4*>(&feat[(size_t)s * 256 + t * 4]);
        acc.x += v.x; acc.y += v.y; acc.z += v.z; acc.w += v.w;
    }

    const int deg = end - start;
    const float inv = (deg > 0) ? 1.0f / (float)deg : 0.0f;
    acc.x *= inv; acc.y *= inv; acc.z *= inv; acc.w *= inv;

    *reinterpret_cast<float4*>(&out[(size_t)d * 256 + t * 4]) = acc;
}

// ---------------------------------------------------------------------------
// TF32 helpers
// ---------------------------------------------------------------------------
__device__ __forceinline__ uint32_t f2tf32(float f) {
    uint32_t r;
    asm("cvt.rna.tf32.f32 %0, %1;" : "=r"(r) : "f"(f));
    return r;
}

__device__ __forceinline__ void mma_tf32(float c[4], const uint32_t a[4], const uint32_t b[2]) {
    asm volatile(
        "mma.sync.aligned.m16n8k8.row.col.f32.tf32.tf32.f32 "
        "{%0,%1,%2,%3}, {%4,%5,%6,%7}, {%8,%9}, {%0,%1,%2,%3};\n"
        : "+f"(c[0]), "+f"(c[1]), "+f"(c[2]), "+f"(c[3])
        : "r"(a[0]), "r"(a[1]), "r"(a[2]), "r"(a[3]), "r"(b[0]), "r"(b[1]));
}

// ---------------------------------------------------------------------------
// Layer-1 GEMM (3xTF32 tensor core):
//   h = relu( [x_dst | h_neigh] @ [W_self ; W_neigh] + b )
// M=11264, N=256, K=512.  CTA tile 128x64, BK=16, 8 warps (warp tile 64x16).
// ---------------------------------------------------------------------------
#define G1_BM 128
#define G1_BN 64
#define G1_BK 16
#define SA 136   // As[k][m] row stride (pad for conflict-free frag LDS)
#define SB 72    // Bs[k][n] row stride

__global__ __launch_bounds__(256) void gemm1_tf32_kernel(
    const float* __restrict__ x,        // [N_SRC1, 256]
    const float* __restrict__ hneigh,   // [N_DST1, 256]
    const float* __restrict__ Wself,    // [256, 256]
    const float* __restrict__ Wneigh,   // [256, 256]
    const float* __restrict__ bias,     // [256]
    float* __restrict__ out)            // [N_DST1, 256]
{
    const int bx = blockIdx.x;          // 0..3   (N tiles of 64)
    const int by = blockIdx.y;          // 0..87  (M tiles of 128)

    const int tid  = threadIdx.x;
    const int warp = tid >> 5;
    const int lane = tid & 31;
    const int wm   = warp >> 2;         // 0..1  (64 rows each)
    const int wn   = warp & 3;          // 0..3  (16 cols each)
    const int g    = lane >> 2;         // 0..7
    const int tg   = lane & 3;          // 0..3

    __shared__ float As_hi[G1_BK * SA];
    __shared__ float As_lo[G1_BK * SA];
    __shared__ float Bs_hi[G1_BK * SB];
    __shared__ float Bs_lo[G1_BK * SB];

    float acc[4][2][4];
#pragma unroll
    for (int i = 0; i < 4; ++i)
#pragma unroll
        for (int j = 0; j < 2; ++j)
#pragma unroll
            for (int r = 0; r < 4; ++r) acc[i][j][r] = 0.f;

    // Staging index maps
    const int a_row = tid >> 2;             // 0..63  (+64 for second load)
    const int a_k   = (tid & 3) * 4;        // 0,4,8,12
    const int b_k   = tid >> 4;             // 0..15
    const int b_n   = (tid & 15) * 4;       // 0..60

    // Prefetch first tile
    float4 av0, av1, bv0;
    {
        const float* Asrc = x;
        const float* Bsrc = Wself;
        av0 = *reinterpret_cast<const float4*>(&Asrc[(size_t)(by * G1_BM + a_row) * 256 + a_k]);
        av1 = *reinterpret_cast<const float4*>(&Asrc[(size_t)(by * G1_BM + a_row + 64) * 256 + a_k]);
        bv0 = *reinterpret_cast<const float4*>(&Bsrc[(size_t)b_k * 256 + bx * G1_BN + b_n]);
    }

    for (int k0 = 0; k0 < 512; k0 += G1_BK) {
        // Convert + store staged tile to shared ([k][m] / [k][n])
        {
            const float a0[4] = {av0.x, av0.y, av0.z, av0.w};
            const float a1[4] = {av1.x, av1.y, av1.z, av1.w};
#pragma unroll
            for (int j = 0; j < 4; ++j) {
                uint32_t h0 = f2tf32(a0[j]);
                uint32_t l0 = f2tf32(a0[j] - __uint_as_float(h0));
                As_hi[(a_k + j) * SA + a_row] = __uint_as_float(h0);
                As_lo[(a_k + j) * SA + a_row] = __uint_as_float(l0);
                uint32_t h1 = f2tf32(a1[j]);
                uint32_t l1 = f2tf32(a1[j] - __uint_as_float(h1));
                As_hi[(a_k + j) * SA + a_row + 64] = __uint_as_float(h1);
                As_lo[(a_k + j) * SA + a_row + 64] = __uint_as_float(l1);
            }
            const float b0[4] = {bv0.x, bv0.y, bv0.z, bv0.w};
            float bh[4], bl[4];
#pragma unroll
            for (int j = 0; j < 4; ++j) {
                uint32_t h = f2tf32(b0[j]);
                bh[j] = __uint_as_float(h);
                bl[j] = __uint_as_float(f2tf32(b0[j] - bh[j]));
            }
            *reinterpret_cast<float4*>(&Bs_hi[b_k * SB + b_n]) = make_float4(bh[0], bh[1], bh[2], bh[3]);
            *reinterpret_cast<float4*>(&Bs_lo[b_k * SB + b_n]) = make_float4(bl[0], bl[1], bl[2], bl[3]);
        }
        __syncthreads();

        // Prefetch next tile (LDG latency overlaps MMA below)
        const int kn = k0 + G1_BK;
        if (kn < 512) {
            const float* Asrc = (kn < 256) ? x : hneigh;
            const float* Bsrc = (kn < 256) ? Wself : Wneigh;
            const int kk = kn & 255;
            av0 = *reinterpret_cast<const float4*>(&Asrc[(size_t)(by * G1_BM + a_row) * 256 + kk + a_k]);
            av1 = *reinterpret_cast<const float4*>(&Asrc[(size_t)(by * G1_BM + a_row + 64) * 256 + kk + a_k]);
            bv0 = *reinterpret_cast<const float4*>(&Bsrc[(size_t)(kk + b_k) * 256 + bx * G1_BN + b_n]);
        }

        // Two k-steps of 8
#pragma unroll
        for (int s = 0; s < 2; ++s) {
            uint32_t ahi[4][4], alo[4][4];
#pragma unroll
            for (int i = 0; i < 4; ++i) {
                const int m = wm * 64 + i * 16 + g;
                const int k = s * 8 + tg;
                ahi[i][0] = __float_as_uint(As_hi[k * SA + m]);
                ahi[i][1] = __float_as_uint(As_hi[k * SA + m + 8]);
                ahi[i][2] = __float_as_uint(As_hi[(k + 4) * SA + m]);
                ahi[i][3] = __float_as_uint(As_hi[(k + 4) * SA + m + 8]);
                alo[i][0] = __float_as_uint(As_lo[k * SA + m]);
                alo[i][1] = __float_as_uint(As_lo[k * SA + m + 8]);
                alo[i][2] = __float_as_uint(As_lo[(k + 4) * SA + m]);
                alo[i][3] = __float_as_uint(As_lo[(k + 4) * SA + m + 8]);
            }
            uint32_t bhi[2][2], blo[2][2];
#pragma unroll
            for (int j = 0; j < 2; ++j) {
                const int n = wn * 16 + j * 8 + g;
                const int k = s * 8 + tg;
                bhi[j][0] = __float_as_uint(Bs_hi[k * SB + n]);
                bhi[j][1] = __float_as_uint(Bs_hi[(k + 4) * SB + n]);
                blo[j][0] = __float_as_uint(Bs_lo[k * SB + n]);
                blo[j][1] = __float_as_uint(Bs_lo[(k + 4) * SB + n]);
            }
            // 3xTF32: lo*hi + hi*lo + hi*hi
#pragma unroll
            for (int i = 0; i < 4; ++i)
#pragma unroll
                for (int j = 0; j < 2; ++j) mma_tf32(acc[i][j], alo[i], bhi[j]);
#pragma unroll
            for (int i = 0; i < 4; ++i)
#pragma unroll
                for (int j = 0; j < 2; ++j) mma_tf32(acc[i][j], ahi[i], blo[j]);
#pragma unroll
            for (int i = 0; i < 4; ++i)
#pragma unroll
                for (int j = 0; j < 2; ++j) mma_tf32(acc[i][j], ahi[i], bhi[j]);
        }
        __syncthreads();
    }

    // Epilogue: +bias, relu, float2 stores
#pragma unroll
    for (int i = 0; i < 4; ++i) {
#pragma unroll
        for (int j = 0; j < 2; ++j) {
            const int col = bx * G1_BN + wn * 16 + j * 8 + tg * 2;
            const float bx0 = __ldg(&bias[col]);
            const float bx1 = __ldg(&bias[col + 1]);
            const int r0 = by * G1_BM + wm * 64 + i * 16 + g;
            float2 v0;
            v0.x = fmaxf(acc[i][j][0] + bx0, 0.f);
            v0.y = fmaxf(acc[i][j][1] + bx1, 0.f);
            *reinterpret_cast<float2*>(&out[(size_t)r0 * 256 + col]) = v0;
            float2 v1;
            v1.x = fmaxf(acc[i][j][2] + bx0, 0.f);
            v1.y = fmaxf(acc[i][j][3] + bx1, 0.f);
            *reinterpret_cast<float2*>(&out[(size_t)(r0 + 8) * 256 + col]) = v1;
        }
    }
}

// ---------------------------------------------------------------------------
// Layer-2 output GEMM: out[1024,47] = h[:1024] @ Ws2 + hneigh2 @ Wn2 + b2
// 64 blocks x 16 rows, 192 threads (tx = col 0..47, ty = row group 0..3).
// W transposed into shared for float4 inner loop.
// ---------------------------------------------------------------------------
#define GB_M 16
#define GB_K 128
#define SWT 132
#define SA2 132

__global__ __launch_bounds__(192) void gemm2_kernel(
    const float* __restrict__ h,        // [N_DST1, 256]
    const float* __restrict__ hneigh2,  // [N_DST2, 256]
    const float* __restrict__ Ws,       // [256, 47]
    const float* __restrict__ Wn,       // [256, 47]
    const float* __restrict__ bias,     // [47]
    float* __restrict__ out)            // [N_DST2, 47]
{
    const int row0 = blockIdx.x * GB_M;
    const int tid  = threadIdx.x;
    const int tx   = tid % 48;          // col
    const int ty   = tid / 48;          // 0..3 row group

    __shared__ float As2[GB_M * SA2];
    __shared__ float WsT[48 * SWT];

    float acc[4] = {0.f, 0.f, 0.f, 0.f};

    for (int kc = 0; kc < 4; ++kc) {
        const float* Asrc = (kc < 2) ? h : hneigh2;
        const float* Wsrc = (kc < 2) ? Ws : Wn;
        const int kk = (kc & 1) * GB_K;

        // Stage A rows (coalesced)
        for (int i = tid; i < GB_M * GB_K; i += 192) {
            const int r = i >> 7, k = i & 127;
            As2[r * SA2 + k] = Asrc[(size_t)(row0 + r) * 256 + kk + k];
        }
        // Stage W transposed (coalesced over c)
        for (int i = tid; i < 47 * GB_K; i += 192) {
            const int k = i / 47, c = i - k * 47;
            WsT[c * SWT + k] = Wsrc[(size_t)(kk + k) * 47 + c];
        }
        __syncthreads();

        if (tx < 47) {
#pragma unroll 8
            for (int k4 = 0; k4 < GB_K / 4; ++k4) {
                const float4 w4 = *reinterpret_cast<const float4*>(&WsT[tx * SWT + k4 * 4]);
#pragma unroll
                for (int r = 0; r < 4; ++r) {
                    const float4 a4 = *reinterpret_cast<const float4*>(&As2[(ty * 4 + r) * SA2 + k4 * 4]);
                    acc[r] += a4.x * w4.x + a4.y * w4.y + a4.z * w4.z + a4.w * w4.w;
                }
            }
        }
        __syncthreads();
    }

    if (tx < 47) {
        const float b = __ldg(&bias[tx]);
#pragma unroll
        for (int r = 0; r < 4; ++r)
            out[(size_t)(row0 + ty * 4 + r) * 47 + tx] = acc[r] + b;
    }
}

// ---------------------------------------------------------------------------
// Launch
// ---------------------------------------------------------------------------
extern "C" void kernel_launch(void* const* d_in, const int* in_sizes, int n_in,
                              void* d_out, int out_size)
{
    const float* x       = (const float*)d_in[0];
    const int*   src1    = (const int*)  d_in[1];
    const int*   dst1    = (const int*)  d_in[2];
    const int*   src2    = (const int*)  d_in[3];
    const int*   dst2    = (const int*)  d_in[4];
    const float* Wself1  = (const float*)d_in[5];
    const float* Wneigh1 = (const float*)d_in[6];
    const float* b1      = (const float*)d_in[7];
    const float* Wself2  = (const float*)d_in[8];
    const float* Wneigh2 = (const float*)d_in[9];
    const float* b2      = (const float*)d_in[10];
    float* out = (float*)d_out;

    float* hneigh1; cudaGetSymbolAddress((void**)&hneigh1, g_hneigh1);
    float* hbuf;    cudaGetSymbolAddress((void**)&hbuf,    g_h);
    float* hneigh2; cudaGetSymbolAddress((void**)&hneigh2, g_hneigh2);

    // Layer 1: neighbor mean aggregation over x
    agg_mean_kernel<<<N_DST1, 64>>>(x, src1, dst1, N_E1, hneigh1);

    // Layer 1: 3xTF32 tensor-core GEMM + bias + relu
    dim3 g1(H_DIM / G1_BN, N_DST1 / G1_BM);   // (4, 88)
    gemm1_tf32_kernel<<<g1, 256>>>(x, hneigh1, Wself1, Wneigh1, b1, hbuf);

    // Layer 2: neighbor mean aggregation over h
    agg_mean_kernel<<<N_DST2, 64>>>(hbuf, src2, dst2, N_E2, hneigh2);

    // Layer 2: output GEMM
    gemm2_kernel<<<N_DST2 / GB_M, 192>>>(hbuf, hneigh2, Wself2, Wneigh2, b2, out);
}